// round 1
// baseline (speedup 1.0000x reference)
#include <cuda_runtime.h>

// Problem constants
#define B_   2
#define S_   4096
#define D_   1024
#define H_   16
#define DH_  64
#define DIL_ 4
#define L_   1024        // S/DIL (pad = 0 since 4096 % 4 == 0)
#define R_   8192        // B*DIL*L == B*S total rows

// Scratch (device globals — no allocation allowed)
__device__ float g_q[(size_t)R_ * D_];
__device__ float g_k[(size_t)R_ * D_];
__device__ float g_v[(size_t)R_ * D_];
__device__ float g_ctx[(size_t)R_ * D_];
__device__ float g_atted[(size_t)R_ * D_];

// ---------------------------------------------------------------------------
// Kernel 1: QKV projection. C[r,o] = sum_i xr[r,i] * W[o,i] + b[o]
// xr row r (dilated order) maps to x row ((bb>>2)*4096 + l*4 + (bb&3)).
// 64x64 output tile, BK=16, 256 threads, 4x4 per thread.
// blockIdx.z selects {q,k,v}.
// ---------------------------------------------------------------------------
__global__ void __launch_bounds__(256) qkv_gemm(
    const float* __restrict__ x,
    const float* __restrict__ Wq, const float* __restrict__ bq,
    const float* __restrict__ Wk, const float* __restrict__ bk,
    const float* __restrict__ Wv, const float* __restrict__ bv)
{
    const float* W; const float* bias; float* out;
    if (blockIdx.z == 0)      { W = Wq; bias = bq; out = g_q; }
    else if (blockIdx.z == 1) { W = Wk; bias = bk; out = g_k; }
    else                      { W = Wv; bias = bv; out = g_v; }

    __shared__ float As[16][64];
    __shared__ float Ws[16][64];

    const int tid = threadIdx.x;
    const int tx = tid & 15, ty = tid >> 4;
    const int rm0 = blockIdx.y * 64;   // output rows (xr order)
    const int on0 = blockIdx.x * 64;   // output cols

    const int lrow = tid >> 2;         // 0..63
    const int lk   = (tid & 3) * 4;    // 0,4,8,12

    // xr row -> x row permutation
    const int r  = rm0 + lrow;
    const int bb = r >> 10;
    const int l  = r & 1023;
    const int xrow = ((bb >> 2) << 12) + (l << 2) + (bb & 3);
    const float* aptr = x + (size_t)xrow * D_;
    const float* wptr = W + (size_t)(on0 + lrow) * D_;

    float acc[4][4] = {};

    for (int k0 = 0; k0 < D_; k0 += 16) {
        float4 av = *(const float4*)(aptr + k0 + lk);
        float4 wv = *(const float4*)(wptr + k0 + lk);
        As[lk+0][lrow] = av.x; As[lk+1][lrow] = av.y;
        As[lk+2][lrow] = av.z; As[lk+3][lrow] = av.w;
        Ws[lk+0][lrow] = wv.x; Ws[lk+1][lrow] = wv.y;
        Ws[lk+2][lrow] = wv.z; Ws[lk+3][lrow] = wv.w;
        __syncthreads();
        #pragma unroll
        for (int kk = 0; kk < 16; kk++) {
            float4 a = *(const float4*)&As[kk][ty * 4];
            float4 w = *(const float4*)&Ws[kk][tx * 4];
            float ar[4] = {a.x, a.y, a.z, a.w};
            float wr[4] = {w.x, w.y, w.z, w.w};
            #pragma unroll
            for (int i = 0; i < 4; i++)
                #pragma unroll
                for (int j = 0; j < 4; j++)
                    acc[i][j] += ar[i] * wr[j];
        }
        __syncthreads();
    }

    float4 b4 = *(const float4*)(bias + on0 + tx * 4);
    #pragma unroll
    for (int i = 0; i < 4; i++) {
        int orow = rm0 + ty * 4 + i;
        float4 o;
        o.x = acc[i][0] + b4.x; o.y = acc[i][1] + b4.y;
        o.z = acc[i][2] + b4.z; o.w = acc[i][3] + b4.w;
        *(float4*)(out + (size_t)orow * D_ + on0 + tx * 4) = o;
    }
}

// ---------------------------------------------------------------------------
// Kernel 2: attention per (bb, h). Flash style: 64-query tile per block,
// stream K/V in 64-key tiles, online softmax. Q pre-scaled by 1/sqrt(dh).
// Smem: Qs/Ks transposed [d][row] for conflict-free float4 reads in S=QK^T;
// P (written post-softmax) aliases the Ks buffer; Vs natural [key][d].
// ---------------------------------------------------------------------------
__global__ void __launch_bounds__(256) attn_kernel()
{
    __shared__ float Qs[64 * 64];
    __shared__ float Ks[64 * 64];   // reused as P after scores are consumed
    __shared__ float Vs[64 * 64];

    const int tid = threadIdx.x;
    const int tx = tid & 15, ty = tid >> 4;
    const int bbh = blockIdx.y;
    const int bb = bbh >> 4;        // / H
    const int h  = bbh & 15;
    const int q0 = blockIdx.x * 64;

    const float* qbase = g_q + (size_t)(bb * L_ + q0) * D_ + h * DH_;
    #pragma unroll
    for (int rep = 0; rep < 4; rep++) {
        int idx = tid + rep * 256;
        int m  = idx >> 4;
        int d4 = (idx & 15) * 4;
        float4 v = *(const float4*)(qbase + (size_t)m * D_ + d4);
        Qs[(d4+0)*64 + m] = v.x * 0.125f;
        Qs[(d4+1)*64 + m] = v.y * 0.125f;
        Qs[(d4+2)*64 + m] = v.z * 0.125f;
        Qs[(d4+3)*64 + m] = v.w * 0.125f;
    }

    float O[4][4] = {};
    float mrun[4], lrun[4];
    #pragma unroll
    for (int i = 0; i < 4; i++) { mrun[i] = -1e30f; lrun[i] = 0.f; }

    const float* kbase = g_k + (size_t)(bb * L_) * D_ + h * DH_;
    const float* vbase = g_v + (size_t)(bb * L_) * D_ + h * DH_;

    for (int kt = 0; kt < 16; kt++) {
        __syncthreads();  // prior iter done reading Ks(P)/Vs
        #pragma unroll
        for (int rep = 0; rep < 4; rep++) {
            int idx = tid + rep * 256;
            int n  = idx >> 4;
            int d4 = (idx & 15) * 4;
            float4 kv = *(const float4*)(kbase + (size_t)(kt*64 + n) * D_ + d4);
            Ks[(d4+0)*64 + n] = kv.x;
            Ks[(d4+1)*64 + n] = kv.y;
            Ks[(d4+2)*64 + n] = kv.z;
            Ks[(d4+3)*64 + n] = kv.w;
            float4 vv = *(const float4*)(vbase + (size_t)(kt*64 + n) * D_ + d4);
            *(float4*)&Vs[n * 64 + d4] = vv;
        }
        __syncthreads();

        // S = (Q * 1/8) @ K^T   (64x64x64)
        float s[4][4] = {};
        #pragma unroll
        for (int d = 0; d < 64; d++) {
            float4 a = *(const float4*)&Qs[d * 64 + ty * 4];
            float4 w = *(const float4*)&Ks[d * 64 + tx * 4];
            float ar[4] = {a.x, a.y, a.z, a.w};
            float wr[4] = {w.x, w.y, w.z, w.w};
            #pragma unroll
            for (int i = 0; i < 4; i++)
                #pragma unroll
                for (int j = 0; j < 4; j++)
                    s[i][j] += ar[i] * wr[j];
        }

        __syncthreads();  // all warps done reading Ks; reuse it for P

        #pragma unroll
        for (int i = 0; i < 4; i++) {
            float mloc = fmaxf(fmaxf(s[i][0], s[i][1]), fmaxf(s[i][2], s[i][3]));
            #pragma unroll
            for (int off = 1; off < 16; off <<= 1)
                mloc = fmaxf(mloc, __shfl_xor_sync(0xffffffffu, mloc, off));
            float mnew = fmaxf(mrun[i], mloc);
            float corr = __expf(mrun[i] - mnew);
            float rsum = 0.f;
            #pragma unroll
            for (int j = 0; j < 4; j++) {
                float p = __expf(s[i][j] - mnew);
                s[i][j] = p;
                rsum += p;
            }
            #pragma unroll
            for (int off = 1; off < 16; off <<= 1)
                rsum += __shfl_xor_sync(0xffffffffu, rsum, off);
            lrun[i] = lrun[i] * corr + rsum;
            mrun[i] = mnew;
            #pragma unroll
            for (int j = 0; j < 4; j++) O[i][j] *= corr;
            *(float4*)&Ks[(ty*4 + i) * 64 + tx * 4] =
                make_float4(s[i][0], s[i][1], s[i][2], s[i][3]);
        }
        __syncthreads();

        // O += P @ V   (64x64x64)
        #pragma unroll
        for (int n = 0; n < 64; n++) {
            float4 v4 = *(const float4*)&Vs[n * 64 + tx * 4];
            float pv[4];
            #pragma unroll
            for (int i = 0; i < 4; i++) pv[i] = Ks[(ty*4 + i) * 64 + n];
            #pragma unroll
            for (int i = 0; i < 4; i++) {
                O[i][0] += pv[i] * v4.x;
                O[i][1] += pv[i] * v4.y;
                O[i][2] += pv[i] * v4.z;
                O[i][3] += pv[i] * v4.w;
            }
        }
    }

    float* obase = g_ctx + (size_t)(bb * L_ + q0) * D_ + h * DH_;
    #pragma unroll
    for (int i = 0; i < 4; i++) {
        float inv = 1.f / lrun[i];
        float4 o = make_float4(O[i][0]*inv, O[i][1]*inv, O[i][2]*inv, O[i][3]*inv);
        *(float4*)(obase + (size_t)(ty*4 + i) * D_ + tx * 4) = o;
    }
}

// ---------------------------------------------------------------------------
// Kernel 3: output projection. atted[r,o] = sum_i ctx_x[r,i]*Wf[o,i] + bf[o]
// ctx is stored in xr order; x-order row r reads ctx row (b*4+(s&3))*L+(s>>2).
// ---------------------------------------------------------------------------
__global__ void __launch_bounds__(256) out_gemm(
    const float* __restrict__ Wf, const float* __restrict__ bf,
    float* __restrict__ atted_ext)
{
    float* atted = atted_ext ? atted_ext : g_atted;

    __shared__ float As[16][64];
    __shared__ float Ws[16][64];

    const int tid = threadIdx.x;
    const int tx = tid & 15, ty = tid >> 4;
    const int rm0 = blockIdx.y * 64;   // x-order rows
    const int on0 = blockIdx.x * 64;

    const int lrow = tid >> 2;
    const int lk   = (tid & 3) * 4;

    const int r = rm0 + lrow;
    const int b = r >> 12;
    const int s = r & 4095;
    const int crow = ((b << 2) + (s & 3)) * L_ + (s >> 2);
    const float* aptr = g_ctx + (size_t)crow * D_;
    const float* wptr = Wf + (size_t)(on0 + lrow) * D_;

    float acc[4][4] = {};

    for (int k0 = 0; k0 < D_; k0 += 16) {
        float4 av = *(const float4*)(aptr + k0 + lk);
        float4 wv = *(const float4*)(wptr + k0 + lk);
        As[lk+0][lrow] = av.x; As[lk+1][lrow] = av.y;
        As[lk+2][lrow] = av.z; As[lk+3][lrow] = av.w;
        Ws[lk+0][lrow] = wv.x; Ws[lk+1][lrow] = wv.y;
        Ws[lk+2][lrow] = wv.z; Ws[lk+3][lrow] = wv.w;
        __syncthreads();
        #pragma unroll
        for (int kk = 0; kk < 16; kk++) {
            float4 a = *(const float4*)&As[kk][ty * 4];
            float4 w = *(const float4*)&Ws[kk][tx * 4];
            float ar[4] = {a.x, a.y, a.z, a.w};
            float wr[4] = {w.x, w.y, w.z, w.w};
            #pragma unroll
            for (int i = 0; i < 4; i++)
                #pragma unroll
                for (int j = 0; j < 4; j++)
                    acc[i][j] += ar[i] * wr[j];
        }
        __syncthreads();
    }

    float4 b4 = *(const float4*)(bf + on0 + tx * 4);
    #pragma unroll
    for (int i = 0; i < 4; i++) {
        int orow = rm0 + ty * 4 + i;
        float4 o;
        o.x = acc[i][0] + b4.x; o.y = acc[i][1] + b4.y;
        o.z = acc[i][2] + b4.z; o.w = acc[i][3] + b4.w;
        *(float4*)(atted + (size_t)orow * D_ + on0 + tx * 4) = o;
    }
}

// ---------------------------------------------------------------------------
// Kernel 4: final = LayerNorm(atted + x) * gamma + beta. One block per row.
// ---------------------------------------------------------------------------
__global__ void __launch_bounds__(256) ln_kernel(
    const float* __restrict__ x,
    const float* __restrict__ atted_ext,
    const float* __restrict__ gamma, const float* __restrict__ beta,
    float* __restrict__ final_out)
{
    const float* atted = atted_ext ? atted_ext : g_atted;
    const int r = blockIdx.x;
    const float* xa = x     + (size_t)r * D_;
    const float* aa = atted + (size_t)r * D_;
    const int tid = threadIdx.x;

    float v[4];
    float s1 = 0.f, s2 = 0.f;
    #pragma unroll
    for (int i = 0; i < 4; i++) {
        int c = tid + i * 256;
        float val = xa[c] + aa[c];
        v[i] = val;
        s1 += val; s2 += val * val;
    }
    #pragma unroll
    for (int off = 16; off; off >>= 1) {
        s1 += __shfl_xor_sync(0xffffffffu, s1, off);
        s2 += __shfl_xor_sync(0xffffffffu, s2, off);
    }
    __shared__ float red[16];
    int warp = tid >> 5, lane = tid & 31;
    if (lane == 0) { red[warp] = s1; red[8 + warp] = s2; }
    __syncthreads();
    float t1 = 0.f, t2 = 0.f;
    #pragma unroll
    for (int w = 0; w < 8; w++) { t1 += red[w]; t2 += red[8 + w]; }
    float mu  = t1 * (1.f / 1024.f);
    float var = t2 * (1.f / 1024.f) - mu * mu;
    float rstd = rsqrtf(var + 1e-5f);
    #pragma unroll
    for (int i = 0; i < 4; i++) {
        int c = tid + i * 256;
        final_out[(size_t)r * D_ + c] = (v[i] - mu) * rstd * gamma[c] + beta[c];
    }
}

// ---------------------------------------------------------------------------
extern "C" void kernel_launch(void* const* d_in, const int* in_sizes, int n_in,
                              void* d_out, int out_size)
{
    (void)in_sizes; (void)n_in;
    const float* x     = (const float*)d_in[0];
    const float* Wq    = (const float*)d_in[1];
    const float* bq    = (const float*)d_in[2];
    const float* Wk    = (const float*)d_in[3];
    const float* bk    = (const float*)d_in[4];
    const float* Wv    = (const float*)d_in[5];
    const float* bv    = (const float*)d_in[6];
    const float* Wf    = (const float*)d_in[7];
    const float* bf    = (const float*)d_in[8];
    const float* gamma = (const float*)d_in[9];
    const float* beta  = (const float*)d_in[10];
    float* out = (float*)d_out;

    // Output layout: (final, atted) concatenated. If the harness only checks
    // `final`, route atted to the internal scratch buffer instead.
    const long long both = 2LL * R_ * D_;
    float* atted = (out_size >= both) ? (out + (size_t)R_ * D_) : nullptr;

    qkv_gemm<<<dim3(D_ / 64, R_ / 64, 3), 256>>>(x, Wq, bq, Wk, bk, Wv, bv);
    attn_kernel<<<dim3(L_ / 64, B_ * DIL_ * H_), 256>>>();
    out_gemm<<<dim3(D_ / 64, R_ / 64), 256>>>(Wf, bf, atted);
    ln_kernel<<<R_, 256>>>(x, atted, gamma, beta, out);
}

// round 3
// speedup vs baseline: 2.0377x; 2.0377x over previous
#include <cuda_runtime.h>
#include <cstdint>

// Problem constants
#define B_   2
#define S_   4096
#define D_   1024
#define H_   16
#define DH_  64
#define DIL_ 4
#define L_   1024
#define R_   8192

// Scratch (device globals — no allocation allowed)
__device__ float g_q[(size_t)R_ * D_];
__device__ float g_k[(size_t)R_ * D_];
__device__ float g_v[(size_t)R_ * D_];
__device__ float g_ctx[(size_t)R_ * D_];
__device__ float g_atted[(size_t)R_ * D_];

// ---------------------------------------------------------------------------
// Warp-level tf32 MMA helpers (plain sm_103-legal PTX, sm_80+)
// ---------------------------------------------------------------------------
__device__ __forceinline__ uint32_t f2tf32(float f) {
    uint32_t u;
    asm("cvt.rna.tf32.f32 %0, %1;" : "=r"(u) : "f"(f));
    return u;
}

__device__ __forceinline__ void mma_tf32(float c[4], const uint32_t a[4],
                                         const uint32_t b[2]) {
    asm volatile(
        "mma.sync.aligned.m16n8k8.row.col.f32.tf32.tf32.f32 "
        "{%0,%1,%2,%3}, {%4,%5,%6,%7}, {%8,%9}, {%0,%1,%2,%3};"
        : "+f"(c[0]), "+f"(c[1]), "+f"(c[2]), "+f"(c[3])
        : "r"(a[0]), "r"(a[1]), "r"(a[2]), "r"(a[3]), "r"(b[0]), "r"(b[1]));
}

// ---------------------------------------------------------------------------
// tf32 warp-MMA GEMM: C[r, o] = sum_i A'[r, i] * W[o, i] + bias[o]
// CTA tile 128x128, BK=32, 8 warps in 2(m) x 4(n), warp tile 64x32.
// mode 0: A' = xr (dilation-permuted gather from x), out = g_{q,k,v} by bIdx.z
// mode 1: A' = ctx in x-order (gather from g_ctx), out = out_override
// ---------------------------------------------------------------------------
#define LDPAD 36   // floats per SMEM row (32 data + 4 pad): conflict-free

__global__ void __launch_bounds__(256) gemm_mma(
    const float* __restrict__ x,
    const float* __restrict__ Wq, const float* __restrict__ bq,
    const float* __restrict__ Wk, const float* __restrict__ bk,
    const float* __restrict__ Wv, const float* __restrict__ bv,
    float* __restrict__ out_override, int mode)
{
    __shared__ uint32_t As[128 * LDPAD];
    __shared__ uint32_t Bs[128 * LDPAD];

    const int tid  = threadIdx.x;
    const int wid  = tid >> 5;
    const int lane = tid & 31;
    const int lr   = lane >> 2;       // 0..7
    const int lc   = lane & 3;        // 0..3
    const int wm0  = (wid >> 2) * 64; // warp m offset in CTA tile
    const int wn0  = (wid & 3) * 32;  // warp n offset

    const float* W; const float* bias; float* out; const float* A;
    if (mode == 0) {
        A = x;
        if (blockIdx.z == 0)      { W = Wq; bias = bq; out = g_q; }
        else if (blockIdx.z == 1) { W = Wk; bias = bk; out = g_k; }
        else                      { W = Wv; bias = bv; out = g_v; }
    } else {
        A = g_ctx; W = Wq; bias = bq; out = out_override;
    }

    const int rm0 = blockIdx.y * 128;
    const int on0 = blockIdx.x * 128;

    // Staging: 8 threads per row, 4 row-passes of 32.
    const int ldrow = tid >> 3;          // 0..31
    const int ldc4  = (tid & 7) * 4;     // 0,4,...,28
    const float* arow[4];
    const float* brow[4];
    #pragma unroll
    for (int p = 0; p < 4; p++) {
        int r = rm0 + p * 32 + ldrow;
        int src;
        if (mode == 0) {
            int bb = r >> 10, l = r & 1023;
            src = ((bb >> 2) << 12) + (l << 2) + (bb & 3);   // xr row -> x row
        } else {
            int b = r >> 12, s = r & 4095;
            src = ((b << 2) + (s & 3)) * L_ + (s >> 2);      // x row -> ctx row
        }
        arow[p] = A + (size_t)src * D_;
        brow[p] = W + (size_t)(on0 + p * 32 + ldrow) * D_;
    }

    float acc[4][4][4] = {};   // [mf][nf][reg]

    for (int k0 = 0; k0 < D_; k0 += 32) {
        if (k0) __syncthreads();
        #pragma unroll
        for (int p = 0; p < 4; p++) {
            float4 av = *(const float4*)(arow[p] + k0 + ldc4);
            float4 bv4 = *(const float4*)(brow[p] + k0 + ldc4);
            uint4 au = make_uint4(f2tf32(av.x), f2tf32(av.y),
                                  f2tf32(av.z), f2tf32(av.w));
            uint4 bu = make_uint4(f2tf32(bv4.x), f2tf32(bv4.y),
                                  f2tf32(bv4.z), f2tf32(bv4.w));
            *(uint4*)&As[(p * 32 + ldrow) * LDPAD + ldc4] = au;
            *(uint4*)&Bs[(p * 32 + ldrow) * LDPAD + ldc4] = bu;
        }
        __syncthreads();

        #pragma unroll
        for (int kk = 0; kk < 4; kk++) {
            const int kb = kk * 8;
            uint32_t a[4][4], b[4][2];
            #pragma unroll
            for (int mf = 0; mf < 4; mf++) {
                const int r0 = (wm0 + mf * 16 + lr) * LDPAD + kb + lc;
                a[mf][0] = As[r0];
                a[mf][1] = As[r0 + 8 * LDPAD];
                a[mf][2] = As[r0 + 4];
                a[mf][3] = As[r0 + 8 * LDPAD + 4];
            }
            #pragma unroll
            for (int nf = 0; nf < 4; nf++) {
                const int r0 = (wn0 + nf * 8 + lr) * LDPAD + kb + lc;
                b[nf][0] = Bs[r0];
                b[nf][1] = Bs[r0 + 4];
            }
            #pragma unroll
            for (int mf = 0; mf < 4; mf++)
                #pragma unroll
                for (int nf = 0; nf < 4; nf++)
                    mma_tf32(acc[mf][nf], a[mf], b[nf]);
        }
    }

    // Epilogue: bias add + fp32 store.
    #pragma unroll
    for (int mf = 0; mf < 4; mf++) {
        const int row0 = rm0 + wm0 + mf * 16 + lr;
        #pragma unroll
        for (int nf = 0; nf < 4; nf++) {
            const int col = on0 + wn0 + nf * 8 + 2 * lc;
            const float bx = bias[col], by = bias[col + 1];
            float2 o0 = make_float2(acc[mf][nf][0] + bx, acc[mf][nf][1] + by);
            float2 o1 = make_float2(acc[mf][nf][2] + bx, acc[mf][nf][3] + by);
            *(float2*)(out + (size_t)row0 * D_ + col) = o0;
            *(float2*)(out + (size_t)(row0 + 8) * D_ + col) = o1;
        }
    }
}

// ---------------------------------------------------------------------------
// Kernel 2: attention per (bb, h). Flash style, fp32 SIMT (unchanged).
// ---------------------------------------------------------------------------
__global__ void __launch_bounds__(256) attn_kernel()
{
    __shared__ float Qs[64 * 64];
    __shared__ float Ks[64 * 64];
    __shared__ float Vs[64 * 64];

    const int tid = threadIdx.x;
    const int tx = tid & 15, ty = tid >> 4;
    const int bbh = blockIdx.y;
    const int bb = bbh >> 4;
    const int h  = bbh & 15;
    const int q0 = blockIdx.x * 64;

    const float* qbase = g_q + (size_t)(bb * L_ + q0) * D_ + h * DH_;
    #pragma unroll
    for (int rep = 0; rep < 4; rep++) {
        int idx = tid + rep * 256;
        int m  = idx >> 4;
        int d4 = (idx & 15) * 4;
        float4 v = *(const float4*)(qbase + (size_t)m * D_ + d4);
        Qs[(d4+0)*64 + m] = v.x * 0.125f;
        Qs[(d4+1)*64 + m] = v.y * 0.125f;
        Qs[(d4+2)*64 + m] = v.z * 0.125f;
        Qs[(d4+3)*64 + m] = v.w * 0.125f;
    }

    float O[4][4] = {};
    float mrun[4], lrun[4];
    #pragma unroll
    for (int i = 0; i < 4; i++) { mrun[i] = -1e30f; lrun[i] = 0.f; }

    const float* kbase = g_k + (size_t)(bb * L_) * D_ + h * DH_;
    const float* vbase = g_v + (size_t)(bb * L_) * D_ + h * DH_;

    for (int kt = 0; kt < 16; kt++) {
        __syncthreads();
        #pragma unroll
        for (int rep = 0; rep < 4; rep++) {
            int idx = tid + rep * 256;
            int n  = idx >> 4;
            int d4 = (idx & 15) * 4;
            float4 kv = *(const float4*)(kbase + (size_t)(kt*64 + n) * D_ + d4);
            Ks[(d4+0)*64 + n] = kv.x;
            Ks[(d4+1)*64 + n] = kv.y;
            Ks[(d4+2)*64 + n] = kv.z;
            Ks[(d4+3)*64 + n] = kv.w;
            float4 vv = *(const float4*)(vbase + (size_t)(kt*64 + n) * D_ + d4);
            *(float4*)&Vs[n * 64 + d4] = vv;
        }
        __syncthreads();

        float s[4][4] = {};
        #pragma unroll
        for (int d = 0; d < 64; d++) {
            float4 a = *(const float4*)&Qs[d * 64 + ty * 4];
            float4 w = *(const float4*)&Ks[d * 64 + tx * 4];
            float ar[4] = {a.x, a.y, a.z, a.w};
            float wr[4] = {w.x, w.y, w.z, w.w};
            #pragma unroll
            for (int i = 0; i < 4; i++)
                #pragma unroll
                for (int j = 0; j < 4; j++)
                    s[i][j] += ar[i] * wr[j];
        }

        __syncthreads();

        #pragma unroll
        for (int i = 0; i < 4; i++) {
            float mloc = fmaxf(fmaxf(s[i][0], s[i][1]), fmaxf(s[i][2], s[i][3]));
            #pragma unroll
            for (int off = 1; off < 16; off <<= 1)
                mloc = fmaxf(mloc, __shfl_xor_sync(0xffffffffu, mloc, off));
            float mnew = fmaxf(mrun[i], mloc);
            float corr = __expf(mrun[i] - mnew);
            float rsum = 0.f;
            #pragma unroll
            for (int j = 0; j < 4; j++) {
                float p = __expf(s[i][j] - mnew);
                s[i][j] = p;
                rsum += p;
            }
            #pragma unroll
            for (int off = 1; off < 16; off <<= 1)
                rsum += __shfl_xor_sync(0xffffffffu, rsum, off);
            lrun[i] = lrun[i] * corr + rsum;
            mrun[i] = mnew;
            #pragma unroll
            for (int j = 0; j < 4; j++) O[i][j] *= corr;
            *(float4*)&Ks[(ty*4 + i) * 64 + tx * 4] =
                make_float4(s[i][0], s[i][1], s[i][2], s[i][3]);
        }
        __syncthreads();

        #pragma unroll
        for (int n = 0; n < 64; n++) {
            float4 v4 = *(const float4*)&Vs[n * 64 + tx * 4];
            float pv[4];
            #pragma unroll
            for (int i = 0; i < 4; i++) pv[i] = Ks[(ty*4 + i) * 64 + n];
            #pragma unroll
            for (int i = 0; i < 4; i++) {
                O[i][0] += pv[i] * v4.x;
                O[i][1] += pv[i] * v4.y;
                O[i][2] += pv[i] * v4.z;
                O[i][3] += pv[i] * v4.w;
            }
        }
    }

    float* obase = g_ctx + (size_t)(bb * L_ + q0) * D_ + h * DH_;
    #pragma unroll
    for (int i = 0; i < 4; i++) {
        float inv = 1.f / lrun[i];
        float4 o = make_float4(O[i][0]*inv, O[i][1]*inv, O[i][2]*inv, O[i][3]*inv);
        *(float4*)(obase + (size_t)(ty*4 + i) * D_ + tx * 4) = o;
    }
}

// ---------------------------------------------------------------------------
// Kernel 4: final = LayerNorm(atted + x) * gamma + beta.
// ---------------------------------------------------------------------------
__global__ void __launch_bounds__(256) ln_kernel(
    const float* __restrict__ x,
    const float* __restrict__ atted_ext,
    const float* __restrict__ gamma, const float* __restrict__ beta,
    float* __restrict__ final_out)
{
    const float* atted = atted_ext;
    const int r = blockIdx.x;
    const float* xa = x     + (size_t)r * D_;
    const float* aa = atted + (size_t)r * D_;
    const int tid = threadIdx.x;

    float v[4];
    float s1 = 0.f, s2 = 0.f;
    #pragma unroll
    for (int i = 0; i < 4; i++) {
        int c = tid + i * 256;
        float val = xa[c] + aa[c];
        v[i] = val;
        s1 += val; s2 += val * val;
    }
    #pragma unroll
    for (int off = 16; off; off >>= 1) {
        s1 += __shfl_xor_sync(0xffffffffu, s1, off);
        s2 += __shfl_xor_sync(0xffffffffu, s2, off);
    }
    __shared__ float red[16];
    int warp = tid >> 5, lane = tid & 31;
    if (lane == 0) { red[warp] = s1; red[8 + warp] = s2; }
    __syncthreads();
    float t1 = 0.f, t2 = 0.f;
    #pragma unroll
    for (int w = 0; w < 8; w++) { t1 += red[w]; t2 += red[8 + w]; }
    float mu  = t1 * (1.f / 1024.f);
    float var = t2 * (1.f / 1024.f) - mu * mu;
    float rstd = rsqrtf(var + 1e-5f);
    #pragma unroll
    for (int i = 0; i < 4; i++) {
        int c = tid + i * 256;
        final_out[(size_t)r * D_ + c] = (v[i] - mu) * rstd * gamma[c] + beta[c];
    }
}

// ---------------------------------------------------------------------------
extern "C" void kernel_launch(void* const* d_in, const int* in_sizes, int n_in,
                              void* d_out, int out_size)
{
    (void)in_sizes; (void)n_in;
    const float* x     = (const float*)d_in[0];
    const float* Wq    = (const float*)d_in[1];
    const float* bq    = (const float*)d_in[2];
    const float* Wk    = (const float*)d_in[3];
    const float* bk    = (const float*)d_in[4];
    const float* Wv    = (const float*)d_in[5];
    const float* bv    = (const float*)d_in[6];
    const float* Wf    = (const float*)d_in[7];
    const float* bf    = (const float*)d_in[8];
    const float* gamma = (const float*)d_in[9];
    const float* beta  = (const float*)d_in[10];
    float* out = (float*)d_out;

    const long long both = 2LL * R_ * D_;
    float* atted = (out_size >= both) ? (out + (size_t)R_ * D_) : nullptr;
    if (!atted) {
        static float* h_atted_ptr = nullptr;
        if (!h_atted_ptr) cudaGetSymbolAddress((void**)&h_atted_ptr, g_atted);
        atted = h_atted_ptr;
    }

    // QKV projections (tf32 warp MMA)
    gemm_mma<<<dim3(D_/128, R_/128, 3), 256>>>(
        x, Wq, bq, Wk, bk, Wv, bv, nullptr, 0);
    // Attention (fp32 SIMT)
    attn_kernel<<<dim3(L_/64, B_ * DIL_ * H_), 256>>>();
    // Output projection (tf32 warp MMA)
    gemm_mma<<<dim3(D_/128, R_/128, 1), 256>>>(
        x, Wf, bf, nullptr, nullptr, nullptr, nullptr, atted, 1);
    ln_kernel<<<R_, 256>>>(x, atted, gamma, beta, out);
}

// round 4
// speedup vs baseline: 2.9969x; 1.4707x over previous
#include <cuda_runtime.h>
#include <cstdint>

// Problem constants
#define B_   2
#define S_   4096
#define D_   1024
#define H_   16
#define DH_  64
#define DIL_ 4
#define L_   1024
#define R_   8192

// Scratch (device globals — no allocation allowed)
__device__ float g_q[(size_t)R_ * D_];
__device__ float g_k[(size_t)R_ * D_];
__device__ float g_v[(size_t)R_ * D_];
__device__ float g_ctx[(size_t)R_ * D_];
__device__ float g_atted[(size_t)R_ * D_];

// ---------------------------------------------------------------------------
// Warp-level tf32 MMA helpers (plain sm_103-legal PTX, sm_80+)
// ---------------------------------------------------------------------------
__device__ __forceinline__ uint32_t f2tf32(float f) {
    uint32_t u;
    asm("cvt.rna.tf32.f32 %0, %1;" : "=r"(u) : "f"(f));
    return u;
}

__device__ __forceinline__ void mma_tf32(float c[4], const uint32_t a[4],
                                         const uint32_t b[2]) {
    asm volatile(
        "mma.sync.aligned.m16n8k8.row.col.f32.tf32.tf32.f32 "
        "{%0,%1,%2,%3}, {%4,%5,%6,%7}, {%8,%9}, {%0,%1,%2,%3};"
        : "+f"(c[0]), "+f"(c[1]), "+f"(c[2]), "+f"(c[3])
        : "r"(a[0]), "r"(a[1]), "r"(a[2]), "r"(a[3]), "r"(b[0]), "r"(b[1]));
}

// ---------------------------------------------------------------------------
// tf32 warp-MMA GEMM (unchanged from R2): C[r,o] = sum_i A'[r,i]*W[o,i] + b[o]
// ---------------------------------------------------------------------------
#define LDPAD 36

__global__ void __launch_bounds__(256) gemm_mma(
    const float* __restrict__ x,
    const float* __restrict__ Wq, const float* __restrict__ bq,
    const float* __restrict__ Wk, const float* __restrict__ bk,
    const float* __restrict__ Wv, const float* __restrict__ bv,
    float* __restrict__ out_override, int mode)
{
    __shared__ uint32_t As[128 * LDPAD];
    __shared__ uint32_t Bs[128 * LDPAD];

    const int tid  = threadIdx.x;
    const int wid  = tid >> 5;
    const int lane = tid & 31;
    const int lr   = lane >> 2;
    const int lc   = lane & 3;
    const int wm0  = (wid >> 2) * 64;
    const int wn0  = (wid & 3) * 32;

    const float* W; const float* bias; float* out; const float* A;
    if (mode == 0) {
        A = x;
        if (blockIdx.z == 0)      { W = Wq; bias = bq; out = g_q; }
        else if (blockIdx.z == 1) { W = Wk; bias = bk; out = g_k; }
        else                      { W = Wv; bias = bv; out = g_v; }
    } else {
        A = g_ctx; W = Wq; bias = bq; out = out_override;
    }

    const int rm0 = blockIdx.y * 128;
    const int on0 = blockIdx.x * 128;

    const int ldrow = tid >> 3;
    const int ldc4  = (tid & 7) * 4;
    const float* arow[4];
    const float* brow[4];
    #pragma unroll
    for (int p = 0; p < 4; p++) {
        int r = rm0 + p * 32 + ldrow;
        int src;
        if (mode == 0) {
            int bb = r >> 10, l = r & 1023;
            src = ((bb >> 2) << 12) + (l << 2) + (bb & 3);
        } else {
            int b = r >> 12, s = r & 4095;
            src = ((b << 2) + (s & 3)) * L_ + (s >> 2);
        }
        arow[p] = A + (size_t)src * D_;
        brow[p] = W + (size_t)(on0 + p * 32 + ldrow) * D_;
    }

    float acc[4][4][4] = {};

    for (int k0 = 0; k0 < D_; k0 += 32) {
        if (k0) __syncthreads();
        #pragma unroll
        for (int p = 0; p < 4; p++) {
            float4 av = *(const float4*)(arow[p] + k0 + ldc4);
            float4 bv4 = *(const float4*)(brow[p] + k0 + ldc4);
            uint4 au = make_uint4(f2tf32(av.x), f2tf32(av.y),
                                  f2tf32(av.z), f2tf32(av.w));
            uint4 bu = make_uint4(f2tf32(bv4.x), f2tf32(bv4.y),
                                  f2tf32(bv4.z), f2tf32(bv4.w));
            *(uint4*)&As[(p * 32 + ldrow) * LDPAD + ldc4] = au;
            *(uint4*)&Bs[(p * 32 + ldrow) * LDPAD + ldc4] = bu;
        }
        __syncthreads();

        #pragma unroll
        for (int kk = 0; kk < 4; kk++) {
            const int kb = kk * 8;
            uint32_t a[4][4], b[4][2];
            #pragma unroll
            for (int mf = 0; mf < 4; mf++) {
                const int r0 = (wm0 + mf * 16 + lr) * LDPAD + kb + lc;
                a[mf][0] = As[r0];
                a[mf][1] = As[r0 + 8 * LDPAD];
                a[mf][2] = As[r0 + 4];
                a[mf][3] = As[r0 + 8 * LDPAD + 4];
            }
            #pragma unroll
            for (int nf = 0; nf < 4; nf++) {
                const int r0 = (wn0 + nf * 8 + lr) * LDPAD + kb + lc;
                b[nf][0] = Bs[r0];
                b[nf][1] = Bs[r0 + 4];
            }
            #pragma unroll
            for (int mf = 0; mf < 4; mf++)
                #pragma unroll
                for (int nf = 0; nf < 4; nf++)
                    mma_tf32(acc[mf][nf], a[mf], b[nf]);
        }
    }

    #pragma unroll
    for (int mf = 0; mf < 4; mf++) {
        const int row0 = rm0 + wm0 + mf * 16 + lr;
        #pragma unroll
        for (int nf = 0; nf < 4; nf++) {
            const int col = on0 + wn0 + nf * 8 + 2 * lc;
            const float bx = bias[col], by = bias[col + 1];
            float2 o0 = make_float2(acc[mf][nf][0] + bx, acc[mf][nf][1] + by);
            float2 o1 = make_float2(acc[mf][nf][2] + bx, acc[mf][nf][3] + by);
            *(float2*)(out + (size_t)row0 * D_ + col) = o0;
            *(float2*)(out + (size_t)(row0 + 8) * D_ + col) = o1;
        }
    }
}

// ---------------------------------------------------------------------------
// Attention via tf32 warp MMA. Block = 128 threads (4 warps), q-tile 64.
// Warp w owns queries [q0 + 16w, q0 + 16w + 16). Q frags live in registers.
// Ks buffer (64x68 words) triple-duty: Q staging, K tile, P (post-softmax).
// ---------------------------------------------------------------------------
#define APAD 68

__global__ void __launch_bounds__(128) attn_mma()
{
    __shared__ uint32_t Ks[64 * APAD];   // Q staging -> K tile -> P tile
    __shared__ uint32_t Vs[64 * APAD];

    const int tid  = threadIdx.x;
    const int wid  = tid >> 5;
    const int lane = tid & 31;
    const int lr   = lane >> 2;      // 0..7
    const int lc   = lane & 3;       // 0..3
    const int bbh  = blockIdx.y;
    const int bb   = bbh >> 4;
    const int h    = bbh & 15;
    const int q0   = blockIdx.x * 64;

    const int srow = tid >> 1;           // staging row 0..63
    const int scol = (tid & 1) * 32;     // staging col 0 / 32

    // --- Stage Q (x 1/sqrt(dh)) into Ks, pull A-fragments into registers ---
    {
        const float* qg = g_q + (size_t)(bb * L_ + q0 + srow) * D_ + h * DH_ + scol;
        #pragma unroll
        for (int j = 0; j < 8; j++) {
            float4 v = *(const float4*)(qg + j * 4);
            int s0 = srow * APAD + scol + j * 4;
            Ks[s0 + 0] = f2tf32(v.x * 0.125f);
            Ks[s0 + 1] = f2tf32(v.y * 0.125f);
            Ks[s0 + 2] = f2tf32(v.z * 0.125f);
            Ks[s0 + 3] = f2tf32(v.w * 0.125f);
        }
    }
    __syncthreads();
    uint32_t qa[8][4];
    #pragma unroll
    for (int kk = 0; kk < 8; kk++) {
        const int r0 = (wid * 16 + lr) * APAD + kk * 8 + lc;
        qa[kk][0] = Ks[r0];
        qa[kk][1] = Ks[r0 + 8 * APAD];
        qa[kk][2] = Ks[r0 + 4];
        qa[kk][3] = Ks[r0 + 8 * APAD + 4];
    }

    float O[8][4] = {};
    float m0 = -1e30f, m1 = -1e30f, l0 = 0.f, l1 = 0.f;

    const float* kg = g_k + (size_t)(bb * L_) * D_ + h * DH_;
    const float* vg = g_v + (size_t)(bb * L_) * D_ + h * DH_;

    for (int kt = 0; kt < 16; kt++) {
        __syncthreads();   // prior-iter P/V consumers done (and Q frags read)
        {
            const float* kp = kg + (size_t)(kt * 64 + srow) * D_ + scol;
            const float* vp = vg + (size_t)(kt * 64 + srow) * D_ + scol;
            #pragma unroll
            for (int j = 0; j < 8; j++) {
                float4 kv = *(const float4*)(kp + j * 4);
                float4 vv = *(const float4*)(vp + j * 4);
                int s0 = srow * APAD + scol + j * 4;
                Ks[s0 + 0] = f2tf32(kv.x);
                Ks[s0 + 1] = f2tf32(kv.y);
                Ks[s0 + 2] = f2tf32(kv.z);
                Ks[s0 + 3] = f2tf32(kv.w);
                Vs[s0 + 0] = f2tf32(vv.x);
                Vs[s0 + 1] = f2tf32(vv.y);
                Vs[s0 + 2] = f2tf32(vv.z);
                Vs[s0 + 3] = f2tf32(vv.w);
            }
        }
        __syncthreads();

        // --- S = Q @ K^T (16x64 per warp) ---
        float s[8][4] = {};
        #pragma unroll
        for (int kk = 0; kk < 8; kk++) {
            uint32_t b[8][2];
            #pragma unroll
            for (int nf = 0; nf < 8; nf++) {
                const int r0 = (nf * 8 + lr) * APAD + kk * 8 + lc;
                b[nf][0] = Ks[r0];
                b[nf][1] = Ks[r0 + 4];
            }
            #pragma unroll
            for (int nf = 0; nf < 8; nf++)
                mma_tf32(s[nf], qa[kk], b[nf]);
        }
        __syncthreads();   // all warps done reading Ks -> safe to reuse as P

        // --- online softmax in accumulator layout (rows lr, lr+8) ---
        float ml0 = -1e30f, ml1 = -1e30f;
        #pragma unroll
        for (int nf = 0; nf < 8; nf++) {
            ml0 = fmaxf(ml0, fmaxf(s[nf][0], s[nf][1]));
            ml1 = fmaxf(ml1, fmaxf(s[nf][2], s[nf][3]));
        }
        ml0 = fmaxf(ml0, __shfl_xor_sync(0xffffffffu, ml0, 1));
        ml0 = fmaxf(ml0, __shfl_xor_sync(0xffffffffu, ml0, 2));
        ml1 = fmaxf(ml1, __shfl_xor_sync(0xffffffffu, ml1, 1));
        ml1 = fmaxf(ml1, __shfl_xor_sync(0xffffffffu, ml1, 2));
        const float mn0 = fmaxf(m0, ml0), mn1 = fmaxf(m1, ml1);
        const float c0 = __expf(m0 - mn0), c1 = __expf(m1 - mn1);
        float rs0 = 0.f, rs1 = 0.f;
        #pragma unroll
        for (int nf = 0; nf < 8; nf++) {
            s[nf][0] = __expf(s[nf][0] - mn0);
            s[nf][1] = __expf(s[nf][1] - mn0);
            s[nf][2] = __expf(s[nf][2] - mn1);
            s[nf][3] = __expf(s[nf][3] - mn1);
            rs0 += s[nf][0] + s[nf][1];
            rs1 += s[nf][2] + s[nf][3];
        }
        rs0 += __shfl_xor_sync(0xffffffffu, rs0, 1);
        rs0 += __shfl_xor_sync(0xffffffffu, rs0, 2);
        rs1 += __shfl_xor_sync(0xffffffffu, rs1, 1);
        rs1 += __shfl_xor_sync(0xffffffffu, rs1, 2);
        l0 = l0 * c0 + rs0;  m0 = mn0;
        l1 = l1 * c1 + rs1;  m1 = mn1;
        #pragma unroll
        for (int nf = 0; nf < 8; nf++) {
            O[nf][0] *= c0; O[nf][1] *= c0;
            O[nf][2] *= c1; O[nf][3] *= c1;
        }

        // --- P -> SMEM (warp-private rows), reshape to A-fragments ---
        #pragma unroll
        for (int nf = 0; nf < 8; nf++) {
            const int p0 = (wid * 16 + lr) * APAD + nf * 8 + 2 * lc;
            Ks[p0]            = f2tf32(s[nf][0]);
            Ks[p0 + 1]        = f2tf32(s[nf][1]);
            Ks[p0 + 8 * APAD]     = f2tf32(s[nf][2]);
            Ks[p0 + 8 * APAD + 1] = f2tf32(s[nf][3]);
        }
        __syncwarp();

        // --- O += P @ V ---
        #pragma unroll
        for (int kk = 0; kk < 8; kk++) {
            uint32_t a[4];
            const int r0 = (wid * 16 + lr) * APAD + kk * 8 + lc;
            a[0] = Ks[r0];
            a[1] = Ks[r0 + 8 * APAD];
            a[2] = Ks[r0 + 4];
            a[3] = Ks[r0 + 8 * APAD + 4];
            uint32_t b[8][2];
            #pragma unroll
            for (int nf = 0; nf < 8; nf++) {
                b[nf][0] = Vs[(kk * 8 + lc) * APAD + nf * 8 + lr];
                b[nf][1] = Vs[(kk * 8 + lc + 4) * APAD + nf * 8 + lr];
            }
            #pragma unroll
            for (int nf = 0; nf < 8; nf++)
                mma_tf32(O[nf], a, b[nf]);
        }
    }

    // --- normalize and store ctx ---
    const float inv0 = 1.f / l0, inv1 = 1.f / l1;
    float* og = g_ctx + (size_t)(bb * L_ + q0 + wid * 16) * D_ + h * DH_;
    #pragma unroll
    for (int nf = 0; nf < 8; nf++) {
        const int col = nf * 8 + 2 * lc;
        *(float2*)(og + (size_t)lr * D_ + col) =
            make_float2(O[nf][0] * inv0, O[nf][1] * inv0);
        *(float2*)(og + (size_t)(lr + 8) * D_ + col) =
            make_float2(O[nf][2] * inv1, O[nf][3] * inv1);
    }
}

// ---------------------------------------------------------------------------
// Kernel 4: final = LayerNorm(atted + x) * gamma + beta.
// ---------------------------------------------------------------------------
__global__ void __launch_bounds__(256) ln_kernel(
    const float* __restrict__ x,
    const float* __restrict__ atted_ext,
    const float* __restrict__ gamma, const float* __restrict__ beta,
    float* __restrict__ final_out)
{
    const float* atted = atted_ext;
    const int r = blockIdx.x;
    const float* xa = x     + (size_t)r * D_;
    const float* aa = atted + (size_t)r * D_;
    const int tid = threadIdx.x;

    float v[4];
    float s1 = 0.f, s2 = 0.f;
    #pragma unroll
    for (int i = 0; i < 4; i++) {
        int c = tid + i * 256;
        float val = xa[c] + aa[c];
        v[i] = val;
        s1 += val; s2 += val * val;
    }
    #pragma unroll
    for (int off = 16; off; off >>= 1) {
        s1 += __shfl_xor_sync(0xffffffffu, s1, off);
        s2 += __shfl_xor_sync(0xffffffffu, s2, off);
    }
    __shared__ float red[16];
    int warp = tid >> 5, lane = tid & 31;
    if (lane == 0) { red[warp] = s1; red[8 + warp] = s2; }
    __syncthreads();
    float t1 = 0.f, t2 = 0.f;
    #pragma unroll
    for (int w = 0; w < 8; w++) { t1 += red[w]; t2 += red[8 + w]; }
    float mu  = t1 * (1.f / 1024.f);
    float var = t2 * (1.f / 1024.f) - mu * mu;
    float rstd = rsqrtf(var + 1e-5f);
    #pragma unroll
    for (int i = 0; i < 4; i++) {
        int c = tid + i * 256;
        final_out[(size_t)r * D_ + c] = (v[i] - mu) * rstd * gamma[c] + beta[c];
    }
}

// ---------------------------------------------------------------------------
extern "C" void kernel_launch(void* const* d_in, const int* in_sizes, int n_in,
                              void* d_out, int out_size)
{
    (void)in_sizes; (void)n_in;
    const float* x     = (const float*)d_in[0];
    const float* Wq    = (const float*)d_in[1];
    const float* bq    = (const float*)d_in[2];
    const float* Wk    = (const float*)d_in[3];
    const float* bk    = (const float*)d_in[4];
    const float* Wv    = (const float*)d_in[5];
    const float* bv    = (const float*)d_in[6];
    const float* Wf    = (const float*)d_in[7];
    const float* bf    = (const float*)d_in[8];
    const float* gamma = (const float*)d_in[9];
    const float* beta  = (const float*)d_in[10];
    float* out = (float*)d_out;

    const long long both = 2LL * R_ * D_;
    float* atted = (out_size >= both) ? (out + (size_t)R_ * D_) : nullptr;
    if (!atted) {
        static float* h_atted_ptr = nullptr;
        if (!h_atted_ptr) cudaGetSymbolAddress((void**)&h_atted_ptr, g_atted);
        atted = h_atted_ptr;
    }

    // QKV projections (tf32 warp MMA)
    gemm_mma<<<dim3(D_/128, R_/128, 3), 256>>>(
        x, Wq, bq, Wk, bk, Wv, bv, nullptr, 0);
    // Attention (tf32 warp MMA flash)
    attn_mma<<<dim3(L_/64, B_ * DIL_ * H_), 128>>>();
    // Output projection (tf32 warp MMA)
    gemm_mma<<<dim3(D_/128, R_/128, 1), 256>>>(
        x, Wf, bf, nullptr, nullptr, nullptr, nullptr, atted, 1);
    ln_kernel<<<R_, 256>>>(x, atted, gamma, beta, out);
}